// round 2
// baseline (speedup 1.0000x reference)
#include <cuda_runtime.h>

// Problem constants
#define NB 8     // batch
#define TT 8     // time (slice t = TT/2 = 4)
#define V  512   // nodes
#define F  64    // features
#define FH 32    // features per half-pass
#define JT 32    // j-columns per block
#define TPB 512  // 32 j x 16 i-groups
#define IG  16   // i-groups
#define IPG 32   // i per group
#define SU_STRIDE 68  // padded smem row stride (floats)

typedef unsigned long long u64;

// ---- packed f32x2 helpers (Blackwell sm_100+) ----
__device__ __forceinline__ u64 f2add(u64 a, u64 b) {
    u64 r; asm("add.rn.f32x2 %0, %1, %2;" : "=l"(r) : "l"(a), "l"(b)); return r;
}
__device__ __forceinline__ u64 f2fma(u64 a, u64 b, u64 c) {
    u64 r; asm("fma.rn.f32x2 %0, %1, %2, %3;" : "=l"(r) : "l"(a), "l"(b), "l"(c)); return r;
}
__device__ __forceinline__ u64 pk2(float lo, float hi) {
    u64 r; asm("mov.b64 %0, {%1, %2};" : "=l"(r) : "f"(lo), "f"(hi)); return r;
}
__device__ __forceinline__ float psum(u64 v) {
    float lo, hi; asm("mov.b64 {%0, %1}, %2;" : "=f"(lo), "=f"(hi) : "l"(v)); return lo + hi;
}

// One CTA per (n, 32-column j-tile). CTA owns all 512 i rows -> softmax over i
// is fully intra-block. F is processed in two 32-feature passes to keep
// per-thread register state at 64 regs (xjn[16] + a2[16]) so 512 threads fit
// in the 64K-reg file (16 warps/SM).
__global__ __launch_bounds__(TPB, 1)
void graph_learn_kernel(const float* __restrict__ x,
                        const float* __restrict__ a,
                        float* __restrict__ out) {
    extern __shared__ float smem[];
    float* su      = smem;                     // V * SU_STRIDE
    float* stmp    = su + V * SU_STRIDE;       // V * JT
    float* partial = stmp + V * JT;            // IG * 32
    float* colinv  = partial + IG * 32;        // 32
    float* sa      = colinv + 32;              // F

    const int n   = blockIdx.y;
    const int j0  = blockIdx.x * JT;
    const int tid = threadIdx.x;
    const int j   = tid & 31;    // local column
    const int ig  = tid >> 5;    // i-group (0..15), 32 rows each

    // ---- stage xm[n] = x[n, 4, :, :] into smem ----
    const float4* xg = (const float4*)(x + ((size_t)n * TT + TT / 2) * V * F);
    for (int idx = tid; idx < V * F / 4; idx += TPB) {
        int v = idx >> 4, k = idx & 15;
        *(float4*)(su + v * SU_STRIDE + k * 4) = xg[idx];
    }
    if (tid < F) sa[tid] = a[tid];
    __syncthreads();

    const u64 ABS2 = 0x7FFFFFFF7FFFFFFFull;
    const int ibase = ig * IPG;
    float lsum = 0.0f;

#pragma unroll 1
    for (int half = 0; half < 2; half++) {
        const int fo = half * FH;
        // per-thread state for this half: -xj and a, packed pairs
        u64 xjn[FH / 2];
        u64 a2[FH / 2];
        {
            const float* xjrow = su + (j0 + j) * SU_STRIDE + fo;
#pragma unroll
            for (int k = 0; k < FH / 2; k++) {
                float2 w = *(const float2*)(xjrow + 2 * k);
                xjn[k] = pk2(-w.x, -w.y);
                a2[k]  = pk2(sa[fo + 2 * k], sa[fo + 2 * k + 1]);
            }
        }

        for (int ii = 0; ii < IPG; ii++) {
            const int i = ibase + ii;
            const ulonglong2* xi = (const ulonglong2*)(su + i * SU_STRIDE + fo);
            u64 acc0 = 0ull, acc1 = 0ull, acc2 = 0ull, acc3 = 0ull;
#pragma unroll
            for (int k4 = 0; k4 < FH / 4; k4++) {
                ulonglong2 q = xi[k4];  // LDS.128, broadcast across j-lanes
                u64 d0 = f2add(q.x, xjn[2 * k4]) & ABS2;
                u64 d1 = f2add(q.y, xjn[2 * k4 + 1]) & ABS2;
                if (k4 & 1) {
                    acc2 = f2fma(d0, a2[2 * k4], acc2);
                    acc3 = f2fma(d1, a2[2 * k4 + 1], acc3);
                } else {
                    acc0 = f2fma(d0, a2[2 * k4], acc0);
                    acc1 = f2fma(d1, a2[2 * k4 + 1], acc1);
                }
            }
            float s = (psum(acc0) + psum(acc1)) + (psum(acc2) + psum(acc3));
            if (half == 0) {
                stmp[i * JT + j] = s;          // park partial score
            } else {
                float sc = stmp[i * JT + j] + s;
                float t = __expf(fmaxf(sc, 0.0f));   // exp(relu(score))
                lsum += t;
                stmp[i * JT + j] = t;
            }
        }
    }

    // ---- column sums over i (axis=1) ----
    partial[ig * 32 + j] = lsum;
    __syncthreads();
    if (tid < 32) {
        float s = 0.0f;
#pragma unroll
        for (int g = 0; g < IG; g++) s += partial[g * 32 + tid];
        colinv[tid] = 1.0f / s;
    }
    __syncthreads();

    // ---- normalize + write: warp lanes = consecutive j -> coalesced stores ----
    const float inv = colinv[j];
    float* ocol = out + (size_t)n * V * V + j0 + j;
    for (int ii = 0; ii < IPG; ii++) {
        int i = ibase + ii;
        ocol[(size_t)i * V] = stmp[i * JT + j] * inv;
    }
}

extern "C" void kernel_launch(void* const* d_in, const int* in_sizes, int n_in,
                              void* d_out, int out_size) {
    const float* x = (const float*)d_in[0];
    const float* a = (const float*)d_in[1];
    if (n_in >= 2 && in_sizes[0] == F && in_sizes[1] == NB * TT * V * F) {
        const float* t = x; x = a; a = t;
    }
    float* out = (float*)d_out;

    size_t smem_bytes = (size_t)(V * SU_STRIDE + V * JT + IG * 32 + 32 + F) * sizeof(float);
    cudaFuncSetAttribute(graph_learn_kernel,
                         cudaFuncAttributeMaxDynamicSharedMemorySize, (int)smem_bytes);

    dim3 grid(V / JT, NB);
    graph_learn_kernel<<<grid, TPB, smem_bytes>>>(x, a, out);
}

// round 3
// speedup vs baseline: 1.0090x; 1.0090x over previous
#include <cuda_runtime.h>
#include <stdint.h>

// Problem constants
#define NB 8     // batch
#define TT 8     // time (slice t = TT/2 = 4)
#define V  512   // nodes
#define F  64    // features
#define JT 32    // j-columns per block
#define TPB 256  // 32 j-lanes x 8 i-groups
#define IG  8    // i-groups
#define IPG 64   // i per group
#define SU_STRIDE 68  // padded smem row stride (floats), 16B-aligned rows

typedef unsigned long long u64;

// ---- packed f32x2 helpers (Blackwell sm_100+) ----
__device__ __forceinline__ u64 f2add(u64 a, u64 b) {
    u64 r; asm("add.rn.f32x2 %0, %1, %2;" : "=l"(r) : "l"(a), "l"(b)); return r;
}
__device__ __forceinline__ u64 f2fma(u64 a, u64 b, u64 c) {
    u64 r; asm("fma.rn.f32x2 %0, %1, %2, %3;" : "=l"(r) : "l"(a), "l"(b), "l"(c)); return r;
}
__device__ __forceinline__ u64 pk2(float lo, float hi) {
    u64 r; asm("mov.b64 %0, {%1, %2};" : "=l"(r) : "f"(lo), "f"(hi)); return r;
}
__device__ __forceinline__ float psum(u64 v) {
    float lo, hi; asm("mov.b64 {%0, %1}, %2;" : "=f"(lo), "=f"(hi) : "l"(v)); return lo + hi;
}
// Batched shared load: LDS.128 kept in program order (volatile) so ptxas
// issues all row loads back-to-back BEFORE the first consumer -> smem latency
// is pipelined within a single warp instead of exposed 16x per row.
__device__ __forceinline__ void lds128v(uint32_t addr, u64& lo, u64& hi) {
    asm volatile("ld.shared.v2.u64 {%0, %1}, [%2];" : "=l"(lo), "=l"(hi) : "r"(addr));
}

// One CTA per (n, 32-column j-tile). CTA owns all 512 i rows -> softmax over i
// is fully intra-block. Single full-F pass; per-thread holds -xj and a packed
// (128 regs) plus a 64-reg row buffer (launch_bounds(256) => up to 255 regs).
__global__ __launch_bounds__(TPB)
void graph_learn_kernel(const float* __restrict__ x,
                        const float* __restrict__ a,
                        float* __restrict__ out) {
    extern __shared__ float smem[];
    float* su      = smem;                     // V * SU_STRIDE
    float* stmp    = su + V * SU_STRIDE;       // V * JT
    float* partial = stmp + V * JT;            // IG * 32
    float* colinv  = partial + IG * 32;        // 32
    float* sa      = colinv + 32;              // F

    const int n   = blockIdx.y;
    const int j0  = blockIdx.x * JT;
    const int tid = threadIdx.x;
    const int j   = tid & 31;    // local column (lane)
    const int ig  = tid >> 5;    // i-group (0..7), 64 rows each

    // ---- stage xm[n] = x[n, 4, :, :] into smem ----
    const float4* xg = (const float4*)(x + ((size_t)n * TT + TT / 2) * V * F);
    for (int idx = tid; idx < V * F / 4; idx += TPB) {
        int v = idx >> 4, k = idx & 15;
        *(float4*)(su + v * SU_STRIDE + k * 4) = xg[idx];
    }
    if (tid < F) sa[tid] = a[tid];
    __syncthreads();

    // shared-space base address of su for raw LDS
    uint32_t su_addr;
    {
        asm("{ .reg .u64 t; cvta.to.shared.u64 t, %1; cvt.u32.u64 %0, t; }"
            : "=r"(su_addr) : "l"(su));
    }

    // ---- per-thread register state: -xj and a, packed pairs (128 regs) ----
    u64 xjn[F / 2];
    u64 a2[F / 2];
    {
        const float* xjrow = su + (j0 + j) * SU_STRIDE;
#pragma unroll
        for (int k = 0; k < F / 2; k++) {
            float2 w = *(const float2*)(xjrow + 2 * k);
            xjn[k] = pk2(-w.x, -w.y);
            a2[k]  = pk2(sa[2 * k], sa[2 * k + 1]);
        }
    }

    const u64 ABS2 = 0x7FFFFFFF7FFFFFFFull;
    const int ibase = ig * IPG;
    uint32_t rowaddr = su_addr + (uint32_t)ibase * (SU_STRIDE * 4);
    float lsum = 0.0f;

#pragma unroll 1
    for (int ii = 0; ii < IPG; ii++) {
        const int i = ibase + ii;

        // ---- batch-load the whole 64-feature row (16 x LDS.128) ----
        u64 q[F / 2];
#pragma unroll
        for (int k = 0; k < F / 4; k++)
            lds128v(rowaddr + (uint32_t)k * 16, q[2 * k], q[2 * k + 1]);
        rowaddr += SU_STRIDE * 4;

        // ---- 4 independent accumulation chains over 32 packed pairs ----
        u64 acc0 = 0ull, acc1 = 0ull, acc2 = 0ull, acc3 = 0ull;
#pragma unroll
        for (int k = 0; k < F / 8; k++) {
            u64 d0 = f2add(q[4 * k + 0], xjn[4 * k + 0]) & ABS2;
            u64 d1 = f2add(q[4 * k + 1], xjn[4 * k + 1]) & ABS2;
            u64 d2 = f2add(q[4 * k + 2], xjn[4 * k + 2]) & ABS2;
            u64 d3 = f2add(q[4 * k + 3], xjn[4 * k + 3]) & ABS2;
            acc0 = f2fma(d0, a2[4 * k + 0], acc0);
            acc1 = f2fma(d1, a2[4 * k + 1], acc1);
            acc2 = f2fma(d2, a2[4 * k + 2], acc2);
            acc3 = f2fma(d3, a2[4 * k + 3], acc3);
        }
        float s = (psum(acc0) + psum(acc1)) + (psum(acc2) + psum(acc3));
        float t = __expf(fmaxf(s, 0.0f));   // exp(relu(score))
        lsum += t;
        stmp[i * JT + j] = t;
    }

    // ---- column sums over i (axis=1) ----
    partial[ig * 32 + j] = lsum;
    __syncthreads();
    if (tid < 32) {
        float s = 0.0f;
#pragma unroll
        for (int g = 0; g < IG; g++) s += partial[g * 32 + tid];
        colinv[tid] = 1.0f / s;
    }
    __syncthreads();

    // ---- normalize + write: warp lanes = consecutive j -> coalesced stores ----
    const float inv = colinv[j];
    float* ocol = out + (size_t)n * V * V + j0 + j;
    for (int ii = 0; ii < IPG; ii++) {
        int i = ibase + ii;
        ocol[(size_t)i * V] = stmp[i * JT + j] * inv;
    }
}

extern "C" void kernel_launch(void* const* d_in, const int* in_sizes, int n_in,
                              void* d_out, int out_size) {
    const float* x = (const float*)d_in[0];
    const float* a = (const float*)d_in[1];
    if (n_in >= 2 && in_sizes[0] == F && in_sizes[1] == NB * TT * V * F) {
        const float* t = x; x = a; a = t;
    }
    float* out = (float*)d_out;

    size_t smem_bytes = (size_t)(V * SU_STRIDE + V * JT + IG * 32 + 32 + F) * sizeof(float);
    cudaFuncSetAttribute(graph_learn_kernel,
                         cudaFuncAttributeMaxDynamicSharedMemorySize, (int)smem_bytes);

    dim3 grid(V / JT, NB);
    graph_learn_kernel<<<grid, TPB, smem_bytes>>>(x, a, out);
}

// round 4
// speedup vs baseline: 1.2727x; 1.2614x over previous
#include <cuda_runtime.h>
#include <cuda_fp16.h>
#include <stdint.h>

// Problem constants
#define NB 8      // batch
#define TT 8      // time (slice t = TT/2)
#define V  512    // nodes
#define F  64     // features
#define JT 32     // j-columns per block (one per lane)
#define TPB 512   // 32 lanes x 16 i-groups
#define IG  16    // warps per CTA
#define IPG 32    // i-rows per warp
#define YSTRIDE 72  // smem row stride in halfs (144B: 16B-aligned, de-conflicts staging)

// One CTA per (n, 32-col j-tile); CTA owns all 512 i rows -> softmax intra-block.
// xm is staged in SMEM as fp16 (halves the L1tex broadcast-writeback floor,
// which R1-R3 showed is the binding constraint at ~32K cyc/SM with fp32).
__global__ __launch_bounds__(TPB, 1)
void graph_learn_kernel(const float* __restrict__ x,
                        const float* __restrict__ a,
                        float* __restrict__ out) {
    extern __shared__ char smem_raw[];
    __half* yi     = (__half*)smem_raw;                         // V * YSTRIDE halfs
    float* stmp    = (float*)(smem_raw + V * YSTRIDE * 2);      // V * JT
    float* partial = stmp + V * JT;                              // IG * 32
    float* colinv  = partial + IG * 32;                          // 32
    float* sa      = colinv + 32;                                // F

    const int n   = blockIdx.y;
    const int j0  = blockIdx.x * JT;
    const int tid = threadIdx.x;
    const int j   = tid & 31;    // lane = local column
    const int ig  = tid >> 5;    // warp = i-group (0..15)

    // ---- stage xm[n] = x[n, TT/2, :, :] as fp16 into smem ----
    const float4* xg = (const float4*)(x + ((size_t)n * TT + TT / 2) * V * F);
    for (int idx = tid; idx < V * F / 4; idx += TPB) {
        int v = idx >> 4, k = idx & 15;         // k: float4 index within row
        float4 w = xg[idx];
        __half2 h0 = __float22half2_rn(make_float2(w.x, w.y));
        __half2 h1 = __float22half2_rn(make_float2(w.z, w.w));
        *(__half2*)(yi + v * YSTRIDE + k * 4)     = h0;
        *(__half2*)(yi + v * YSTRIDE + k * 4 + 2) = h1;
    }
    if (tid < F) sa[tid] = a[tid];
    __syncthreads();

    // ---- per-thread state: -xj (half2) and a (half2): 64 regs total ----
    __half2 xjn[F / 2];
    __half2 a2[F / 2];
    {
        const __half2* xjrow = (const __half2*)(yi + (j0 + j) * YSTRIDE);
#pragma unroll
        for (int k = 0; k < F / 2; k++) {
            xjn[k] = __hneg2(xjrow[k]);
            a2[k]  = __float22half2_rn(make_float2(sa[2 * k], sa[2 * k + 1]));
        }
    }

    uint32_t yi_addr;
    asm("{ .reg .u64 t; cvta.to.shared.u64 t, %1; cvt.u32.u64 %0, t; }"
        : "=r"(yi_addr) : "l"((const void*)yi));

    const int ibase = ig * IPG;
    uint32_t rowaddr = yi_addr + (uint32_t)ibase * (YSTRIDE * 2);
    float lsum = 0.0f;

#pragma unroll 1
    for (int ii = 0; ii < IPG; ii++) {
        const int i = ibase + ii;

        // ---- batch-load row (128B = 8 x LDS.128, broadcast) ----
        uint32_t q[F / 2];
#pragma unroll
        for (int k = 0; k < F / 8; k++)
            asm volatile("ld.shared.v4.u32 {%0, %1, %2, %3}, [%4];"
                         : "=r"(q[4 * k]), "=r"(q[4 * k + 1]),
                           "=r"(q[4 * k + 2]), "=r"(q[4 * k + 3])
                         : "r"(rowaddr + (uint32_t)k * 16));
        rowaddr += YSTRIDE * 2;

        // ---- 16 independent half2 chains of length 4: HADD2/HABS2/HFMA2 ----
        __half2 acc[8];
#pragma unroll
        for (int k = 0; k < F / 2; k++) {
            __half2 qv = *(__half2*)&q[k];
            __half2 d  = __habs2(__hadd2(qv, xjn[k]));
            if (k < 8) acc[k] = __hmul2(d, a2[k]);
            else       acc[k & 7] = __hfma2(d, a2[k], acc[k & 7]);
        }
        // tree 8 -> 4 in half, then convert + f32 sum
        __half2 b0 = __hadd2(acc[0], acc[1]);
        __half2 b1 = __hadd2(acc[2], acc[3]);
        __half2 b2 = __hadd2(acc[4], acc[5]);
        __half2 b3 = __hadd2(acc[6], acc[7]);
        float2 f0 = __half22float2(b0);
        float2 f1 = __half22float2(b1);
        float2 f2 = __half22float2(b2);
        float2 f3 = __half22float2(b3);
        float s = ((f0.x + f0.y) + (f1.x + f1.y)) + ((f2.x + f2.y) + (f3.x + f3.y));

        float t = __expf(fmaxf(s, 0.0f));   // exp(relu(score))
        lsum += t;
        stmp[i * JT + j] = t;
    }

    // ---- column sums over i (axis=1) ----
    partial[ig * 32 + j] = lsum;
    __syncthreads();
    if (tid < 32) {
        float s = 0.0f;
#pragma unroll
        for (int g = 0; g < IG; g++) s += partial[g * 32 + tid];
        colinv[tid] = 1.0f / s;
    }
    __syncthreads();

    // ---- normalize + write (coalesced over j lanes) ----
    const float inv = colinv[j];
    float* ocol = out + (size_t)n * V * V + j0 + j;
    for (int ii = 0; ii < IPG; ii++) {
        int i = ibase + ii;
        ocol[(size_t)i * V] = stmp[i * JT + j] * inv;
    }
}

extern "C" void kernel_launch(void* const* d_in, const int* in_sizes, int n_in,
                              void* d_out, int out_size) {
    const float* x = (const float*)d_in[0];
    const float* a = (const float*)d_in[1];
    if (n_in >= 2 && in_sizes[0] == F && in_sizes[1] == NB * TT * V * F) {
        const float* t = x; x = a; a = t;
    }
    float* out = (float*)d_out;

    size_t smem_bytes = (size_t)V * YSTRIDE * 2
                      + (size_t)(V * JT + IG * 32 + 32 + F) * sizeof(float);
    cudaFuncSetAttribute(graph_learn_kernel,
                         cudaFuncAttributeMaxDynamicSharedMemorySize, (int)smem_bytes);

    dim3 grid(V / JT, NB);
    graph_learn_kernel<<<grid, TPB, smem_bytes>>>(x, a, out);
}

// round 5
// speedup vs baseline: 1.3393x; 1.0523x over previous
#include <cuda_runtime.h>
#include <cuda_fp16.h>
#include <stdint.h>

// Problem constants
#define NB 8      // batch
#define TT 8      // time (slice t = TT/2)
#define V  512    // nodes
#define F  64     // features
#define JT 32     // j-columns per block (one per lane)
#define TPB 512   // 32 lanes x 16 warps
#define IG  16    // warps per CTA
#define IPG 32    // i-rows per warp (processed 2 at a time)
#define YSTRIDE 72  // smem row stride in halfs (144B, 16B-aligned)

// One CTA per (n, 32-col j-tile); CTA owns all 512 i rows -> softmax intra-block.
// fp16 staging halves the L1tex broadcast floor; 2-row unroll doubles ILP to
// cover the serial per-row epilogue (R4 showed all pipes <=36% = latency-bound).
__global__ __launch_bounds__(TPB, 1)
void graph_learn_kernel(const float* __restrict__ x,
                        const float* __restrict__ a,
                        float* __restrict__ out) {
    extern __shared__ char smem_raw[];
    __half* yi     = (__half*)smem_raw;                         // V * YSTRIDE halfs
    float* stmp    = (float*)(smem_raw + V * YSTRIDE * 2);      // V * JT
    float* partial = stmp + V * JT;                              // IG * 32
    float* colinv  = partial + IG * 32;                          // 32
    float* sa      = colinv + 32;                                // F

    const int n   = blockIdx.y;
    const int j0  = blockIdx.x * JT;
    const int tid = threadIdx.x;
    const int j   = tid & 31;    // lane = local column
    const int ig  = tid >> 5;    // warp = i-group

    // ---- stage xm[n] = x[n, TT/2, :, :] as fp16 into smem ----
    const float4* xg = (const float4*)(x + ((size_t)n * TT + TT / 2) * V * F);
    for (int idx = tid; idx < V * F / 4; idx += TPB) {
        int v = idx >> 4, k = idx & 15;
        float4 w = xg[idx];
        *(__half2*)(yi + v * YSTRIDE + k * 4)     = __float22half2_rn(make_float2(w.x, w.y));
        *(__half2*)(yi + v * YSTRIDE + k * 4 + 2) = __float22half2_rn(make_float2(w.z, w.w));
    }
    if (tid < F) sa[tid] = a[tid];
    __syncthreads();

    // ---- per-thread state: -xj (half2) and a (half2) ----
    __half2 xjn[F / 2];
    __half2 a2[F / 2];
    {
        const __half2* xjrow = (const __half2*)(yi + (j0 + j) * YSTRIDE);
#pragma unroll
        for (int k = 0; k < F / 2; k++) {
            xjn[k] = __hneg2(xjrow[k]);
            a2[k]  = __float22half2_rn(make_float2(sa[2 * k], sa[2 * k + 1]));
        }
    }

    uint32_t yi_addr;
    asm("{ .reg .u64 t; cvta.to.shared.u64 t, %1; cvt.u32.u64 %0, t; }"
        : "=r"(yi_addr) : "l"((const void*)yi));

    const int ibase = ig * IPG;
    uint32_t r0addr = yi_addr + (uint32_t)ibase * (YSTRIDE * 2);
    float lsum = 0.0f;

#pragma unroll 1
    for (int ii = 0; ii < IPG / 2; ii++) {
        const int i0 = ibase + 2 * ii;
        uint32_t r1addr = r0addr + (YSTRIDE * 2);

        __half2 acc0[8], acc1[8];

        // two feature-halves; within each: batch 8 LDS.128 (2 rows x 64B),
        // then 64 interleaved independent fma-pipe ops
#pragma unroll
        for (int h = 0; h < 2; h++) {
            uint32_t q0[16], q1[16];
#pragma unroll
            for (int k = 0; k < 4; k++) {
                asm volatile("ld.shared.v4.u32 {%0, %1, %2, %3}, [%4];"
                             : "=r"(q0[4 * k]), "=r"(q0[4 * k + 1]),
                               "=r"(q0[4 * k + 2]), "=r"(q0[4 * k + 3])
                             : "r"(r0addr + (uint32_t)(h * 64 + k * 16)));
                asm volatile("ld.shared.v4.u32 {%0, %1, %2, %3}, [%4];"
                             : "=r"(q1[4 * k]), "=r"(q1[4 * k + 1]),
                               "=r"(q1[4 * k + 2]), "=r"(q1[4 * k + 3])
                             : "r"(r1addr + (uint32_t)(h * 64 + k * 16)));
            }
#pragma unroll
            for (int k = 0; k < 16; k++) {
                const int kk = h * 16 + k;
                __half2 d0 = __habs2(__hadd2(*(__half2*)&q0[k], xjn[kk]));
                __half2 d1 = __habs2(__hadd2(*(__half2*)&q1[k], xjn[kk]));
                if (h == 0 && k < 8) {
                    acc0[k] = __hmul2(d0, a2[kk]);
                    acc1[k] = __hmul2(d1, a2[kk]);
                } else {
                    acc0[k & 7] = __hfma2(d0, a2[kk], acc0[k & 7]);
                    acc1[k & 7] = __hfma2(d1, a2[kk], acc1[k & 7]);
                }
            }
        }
        r0addr += 2 * (YSTRIDE * 2);

        // ---- interleaved epilogues: 8 -> 2 half2 in fp16, then f32 tail ----
        __half2 p00 = __hadd2(__hadd2(acc0[0], acc0[1]), __hadd2(acc0[2], acc0[3]));
        __half2 p01 = __hadd2(__hadd2(acc0[4], acc0[5]), __hadd2(acc0[6], acc0[7]));
        __half2 p10 = __hadd2(__hadd2(acc1[0], acc1[1]), __hadd2(acc1[2], acc1[3]));
        __half2 p11 = __hadd2(__hadd2(acc1[4], acc1[5]), __hadd2(acc1[6], acc1[7]));
        float2 g00 = __half22float2(p00);
        float2 g01 = __half22float2(p01);
        float2 g10 = __half22float2(p10);
        float2 g11 = __half22float2(p11);
        float s0 = (g00.x + g00.y) + (g01.x + g01.y);
        float s1 = (g10.x + g10.y) + (g11.x + g11.y);
        float t0 = __expf(fmaxf(s0, 0.0f));
        float t1 = __expf(fmaxf(s1, 0.0f));
        lsum += t0 + t1;
        stmp[i0 * JT + j]       = t0;
        stmp[(i0 + 1) * JT + j] = t1;
    }

    // ---- column sums over i (axis=1) ----
    partial[ig * 32 + j] = lsum;
    __syncthreads();
    if (tid < 32) {
        float s = 0.0f;
#pragma unroll
        for (int g = 0; g < IG; g++) s += partial[g * 32 + tid];
        colinv[tid] = 1.0f / s;
    }
    __syncthreads();

    // ---- normalize + write (coalesced over j lanes) ----
    const float inv = colinv[j];
    float* ocol = out + (size_t)n * V * V + j0 + j;
    for (int ii = 0; ii < IPG; ii++) {
        int i = ibase + ii;
        ocol[(size_t)i * V] = stmp[i * JT + j] * inv;
    }
}

extern "C" void kernel_launch(void* const* d_in, const int* in_sizes, int n_in,
                              void* d_out, int out_size) {
    const float* x = (const float*)d_in[0];
    const float* a = (const float*)d_in[1];
    if (n_in >= 2 && in_sizes[0] == F && in_sizes[1] == NB * TT * V * F) {
        const float* t = x; x = a; a = t;
    }
    float* out = (float*)d_out;

    size_t smem_bytes = (size_t)V * YSTRIDE * 2
                      + (size_t)(V * JT + IG * 32 + 32 + F) * sizeof(float);
    cudaFuncSetAttribute(graph_learn_kernel,
                         cudaFuncAttributeMaxDynamicSharedMemorySize, (int)smem_bytes);

    dim3 grid(V / JT, NB);
    graph_learn_kernel<<<grid, TPB, smem_bytes>>>(x, a, out);
}